// round 8
// baseline (speedup 1.0000x reference)
#include <cuda_runtime.h>
#include <cuda_bf16.h>
#include <mma.h>
#include <math.h>
#include <stdint.h>

using namespace nvcuda;

#define TOKENS 4096
#define HIDDEN 2048
#define INTER  1408
#define NE     16
#define TOPK   2
#define MAXROWS (TOKENS * TOPK)

// ---------------- scratch (SMALL statics only — proven envelope) ---------------
__device__ int   g_count[NE];
__device__ int   g_offset[NE + 1];
__device__ int   g_cursor[NE];
__device__ int   g_te[TOKENS * TOPK];
__device__ float g_tw[TOKENS * TOPK];
__device__ int   g_tok[MAXROWS];
__device__ float g_w[MAXROWS];
// activations as bf16 hi/lo (23 MB + 23 MB = same budget as the old fp32 g_act)
__device__ __align__(128) __nv_bfloat16 g_ahi[(size_t)MAXROWS * INTER];
__device__ __align__(128) __nv_bfloat16 g_alo[(size_t)MAXROWS * INTER];

// ---------------- helpers ------------------------------------------------------
// packed fp32x4 -> bf16 hi/lo with vectorized 8B smem stores
__device__ __forceinline__ void split4s(float4 v,
                                        __nv_bfloat16* hp, __nv_bfloat16* lp) {
    __nv_bfloat162 h01 = __floats2bfloat162_rn(v.x, v.y);
    __nv_bfloat162 h23 = __floats2bfloat162_rn(v.z, v.w);
    float2 f01 = __bfloat1622float2(h01);
    float2 f23 = __bfloat1622float2(h23);
    __nv_bfloat162 l01 = __floats2bfloat162_rn(v.x - f01.x, v.y - f01.y);
    __nv_bfloat162 l23 = __floats2bfloat162_rn(v.z - f23.x, v.w - f23.y);
    *(uint2*)hp = make_uint2(*(uint32_t*)&h01, *(uint32_t*)&h23);
    *(uint2*)lp = make_uint2(*(uint32_t*)&l01, *(uint32_t*)&l23);
}

typedef wmma::fragment<wmma::matrix_a, 16, 16, 16, __nv_bfloat16, wmma::row_major> FragA;
typedef wmma::fragment<wmma::matrix_b, 16, 16, 16, __nv_bfloat16, wmma::row_major> FragB;
typedef wmma::fragment<wmma::accumulator, 16, 16, 16, float> FragC;

// ---------------- kernel 1: zero output + counters ------------------------------
__global__ void zero_kernel(float* __restrict__ out) {
    int i = blockIdx.x * blockDim.x + threadIdx.x;
    if (i < TOKENS * HIDDEN) out[i] = 0.0f;
    if (i < NE) g_count[i] = 0;
}

// ---------------- kernel 2: routing ----------------------------------------------
__global__ void route_kernel(const float* __restrict__ logits) {
    int t = blockIdx.x * blockDim.x + threadIdx.x;
    if (t >= TOKENS) return;
    const float* l = logits + (size_t)t * NE;
    int i0 = 0; float m0 = l[0];
#pragma unroll
    for (int i = 1; i < NE; i++) { float x = l[i]; if (x > m0) { m0 = x; i0 = i; } }
    int i1 = (i0 == 0) ? 1 : 0; float m1 = l[i1];
#pragma unroll
    for (int i = 0; i < NE; i++) {
        if (i == i0) continue;
        float x = l[i];
        if (x > m1) { m1 = x; i1 = i; }
    }
    float e  = expf(m1 - m0);
    float w0 = 1.0f / (1.0f + e);
    float w1 = e * w0;
    g_te[t * 2 + 0] = i0;  g_tw[t * 2 + 0] = w0;
    g_te[t * 2 + 1] = i1;  g_tw[t * 2 + 1] = w1;
    atomicAdd(&g_count[i0], 1);
    atomicAdd(&g_count[i1], 1);
}

// ---------------- kernel 3: tiny serial scan -------------------------------------
__global__ void scan_kernel() {
    if (threadIdx.x == 0) {
        int acc = 0;
        g_offset[0] = 0;
        for (int i = 0; i < NE; i++) {
            acc += g_count[i];
            g_offset[i + 1] = acc;
            g_cursor[i] = 0;
        }
    }
}

// ---------------- kernel 4: placement ---------------------------------------------
__global__ void place_kernel() {
    int t = blockIdx.x * blockDim.x + threadIdx.x;
    if (t >= TOKENS) return;
#pragma unroll
    for (int k = 0; k < TOPK; k++) {
        int   e = g_te[t * 2 + k];
        float w = g_tw[t * 2 + k];
        int pos = atomicAdd(&g_cursor[e], 1);
        int idx = g_offset[e] + pos;
        g_tok[idx] = t;
        g_w[idx]   = w;
    }
}

// ================ GEMM1: gate+up, wmma bf16x3 (R6 structure, vectorized splits) ==
// BM=128, BN=64, BK=32. 8 warps: 4(m) x 2(n), warp tile 32x32.
// smem: toks 512 | Ahi 10240 | Alo 10240 | Bgh 4608 | Bgl 4608 | Buh 4608 | Bul 4608
#define LDA 40
#define LDB 72
#define G1_SMEM 39424

__global__ __launch_bounds__(256) void gemm1_wmma(
    const float* __restrict__ hid,
    const float* __restrict__ wg,
    const float* __restrict__ wu)
{
    const int e   = blockIdx.z;
    const int cnt = g_count[e];
    const int m0  = blockIdx.y * 128;
    if (m0 >= cnt) return;
    const int n0   = blockIdx.x * 64;
    const int base = g_offset[e];

    extern __shared__ char sm[];
    int* toks = (int*)sm;
    __nv_bfloat16* Ahi = (__nv_bfloat16*)(sm + 512);
    __nv_bfloat16* Alo = (__nv_bfloat16*)(sm + 10752);
    __nv_bfloat16* Bgh = (__nv_bfloat16*)(sm + 20992);
    __nv_bfloat16* Bgl = (__nv_bfloat16*)(sm + 25600);
    __nv_bfloat16* Buh = (__nv_bfloat16*)(sm + 30208);
    __nv_bfloat16* Bul = (__nv_bfloat16*)(sm + 34816);

    const int tid  = threadIdx.x;
    const int wid  = tid >> 5, lane = tid & 31;
    const int wm   = (wid & 3) * 32;
    const int wn   = (wid >> 2) * 32;

    if (tid < 128) {
        int r = m0 + tid;
        toks[tid] = g_tok[base + ((r < cnt) ? r : 0)];
    }
    __syncthreads();

    FragC accg[2][2], accu[2][2];
#pragma unroll
    for (int mt = 0; mt < 2; mt++)
#pragma unroll
        for (int nt = 0; nt < 2; nt++) {
            wmma::fill_fragment(accg[mt][nt], 0.0f);
            wmma::fill_fragment(accu[mt][nt], 0.0f);
        }

    float4 pfA[4], pfG[2], pfU[2];

    auto LOADG = [&](int k0) {
#pragma unroll
        for (int it = 0; it < 4; it++) {
            int idx = tid + it * 256;
            int row = idx >> 3, c4 = idx & 7;
            pfA[it] = *(const float4*)(hid + (size_t)toks[row] * HIDDEN + k0 + c4 * 4);
        }
#pragma unroll
        for (int it = 0; it < 2; it++) {
            int idx = tid + it * 256;
            int row = idx >> 4, c4 = idx & 15;
            size_t off = (size_t)e * HIDDEN * INTER + (size_t)(k0 + row) * INTER + n0 + c4 * 4;
            pfG[it] = *(const float4*)(wg + off);
            pfU[it] = *(const float4*)(wu + off);
        }
    };
    auto STORES = [&]() {
#pragma unroll
        for (int it = 0; it < 4; it++) {
            int idx = tid + it * 256;
            int row = idx >> 3, c4 = idx & 7;
            split4s(pfA[it], Ahi + row * LDA + c4 * 4, Alo + row * LDA + c4 * 4);
        }
#pragma unroll
        for (int it = 0; it < 2; it++) {
            int idx = tid + it * 256;
            int row = idx >> 4, c4 = idx & 15;
            split4s(pfG[it], Bgh + row * LDB + c4 * 4, Bgl + row * LDB + c4 * 4);
            split4s(pfU[it], Buh + row * LDB + c4 * 4, Bul + row * LDB + c4 * 4);
        }
    };

    LOADG(0);
    const int NS = HIDDEN / 32;   // 64
    for (int s = 0; s < NS; s++) {
        STORES();
        __syncthreads();
        if (s + 1 < NS) LOADG((s + 1) * 32);
#pragma unroll
        for (int kk = 0; kk < 32; kk += 16) {
            FragA ah[2], al[2];
#pragma unroll
            for (int mt = 0; mt < 2; mt++) {
                wmma::load_matrix_sync(ah[mt], Ahi + (wm + mt * 16) * LDA + kk, LDA);
                wmma::load_matrix_sync(al[mt], Alo + (wm + mt * 16) * LDA + kk, LDA);
            }
#pragma unroll
            for (int nt = 0; nt < 2; nt++) {
                FragB bh, bl;
                const int bcol = wn + nt * 16;
                wmma::load_matrix_sync(bh, Bgh + kk * LDB + bcol, LDB);
                wmma::load_matrix_sync(bl, Bgl + kk * LDB + bcol, LDB);
#pragma unroll
                for (int mt = 0; mt < 2; mt++) {
                    wmma::mma_sync(accg[mt][nt], ah[mt], bh, accg[mt][nt]);
                    wmma::mma_sync(accg[mt][nt], al[mt], bh, accg[mt][nt]);
                    wmma::mma_sync(accg[mt][nt], ah[mt], bl, accg[mt][nt]);
                }
                wmma::load_matrix_sync(bh, Buh + kk * LDB + bcol, LDB);
                wmma::load_matrix_sync(bl, Bul + kk * LDB + bcol, LDB);
#pragma unroll
                for (int mt = 0; mt < 2; mt++) {
                    wmma::mma_sync(accu[mt][nt], ah[mt], bh, accu[mt][nt]);
                    wmma::mma_sync(accu[mt][nt], al[mt], bh, accu[mt][nt]);
                    wmma::mma_sync(accu[mt][nt], ah[mt], bl, accu[mt][nt]);
                }
            }
        }
        __syncthreads();
    }

    // epilogue: swiglu in fragments, stage fp32, store bf16 hi/lo activation pairs
    float* stg = (float*)(sm + 512) + wid * 320;   // 16x20 per warp
#pragma unroll
    for (int mt = 0; mt < 2; mt++)
#pragma unroll
        for (int nt = 0; nt < 2; nt++) {
            FragC& G = accg[mt][nt];
            FragC& U = accu[mt][nt];
#pragma unroll
            for (int i = 0; i < G.num_elements; i++) {
                float g = G.x[i];
                G.x[i] = (g / (1.0f + __expf(-g))) * U.x[i];
            }
            wmma::store_matrix_sync(stg, G, 20, wmma::mem_row_major);
            __syncwarp();
            for (int i = lane; i < 128; i += 32) {
                int r = i >> 3, c = (i & 7) * 2;
                int m = m0 + wm + mt * 16 + r;
                if (m < cnt) {
                    float a0 = stg[r * 20 + c], a1 = stg[r * 20 + c + 1];
                    __nv_bfloat162 hv = __floats2bfloat162_rn(a0, a1);
                    float2 hf = __bfloat1622float2(hv);
                    __nv_bfloat162 lv = __floats2bfloat162_rn(a0 - hf.x, a1 - hf.y);
                    size_t off = (size_t)(base + m) * INTER + n0 + wn + nt * 16 + c;
                    *(__nv_bfloat162*)(g_ahi + off) = hv;
                    *(__nv_bfloat162*)(g_alo + off) = lv;
                }
            }
            __syncwarp();
        }
}

// ================ GEMM2: down, wmma bf16x3, BN=128, bf16 A path ==================
// BM=128, BN=128, BK=32. 8 warps: 4(m) x 2(n), warp tile 32x64.
// smem: Ahi 10240 | Alo 10240 | Bh 8704 | Bl 8704 = 37888  (LDB2 = 136)
#define LDB2 136
#define G2_SMEM 37888

__global__ __launch_bounds__(256) void gemm2_wmma(
    const float* __restrict__ wd, float* __restrict__ out)
{
    const int e   = blockIdx.z;
    const int cnt = g_count[e];
    const int m0  = blockIdx.y * 128;
    if (m0 >= cnt) return;
    const int n0   = blockIdx.x * 128;
    const int base = g_offset[e];

    extern __shared__ char sm[];
    __nv_bfloat16* Ahi = (__nv_bfloat16*)(sm);
    __nv_bfloat16* Alo = (__nv_bfloat16*)(sm + 10240);
    __nv_bfloat16* Bh  = (__nv_bfloat16*)(sm + 20480);
    __nv_bfloat16* Bl  = (__nv_bfloat16*)(sm + 29184);

    const int tid  = threadIdx.x;
    const int wid  = tid >> 5, lane = tid & 31;
    const int wm   = (wid & 3) * 32;
    const int wn   = (wid >> 2) * 64;

    // A loader: row = tid>>1 (0..127), two 16B chunks of the 32-col row
    const int ar = tid >> 1;
    const int aq = (tid & 1) * 2;
    int arowm = m0 + ar;
    const int arow = base + ((arowm < cnt) ? arowm : 0);
    // B loader: row = tid>>3 (0..31), 16 fp32 cols per thread
    const int br = tid >> 3;
    const int bc = (tid & 7) * 16;

    FragC acc[2][4];
#pragma unroll
    for (int mt = 0; mt < 2; mt++)
#pragma unroll
        for (int nt = 0; nt < 4; nt++) wmma::fill_fragment(acc[mt][nt], 0.0f);

    uint4 pfAh[2], pfAl[2];
    float4 pfB[4];

    auto LOADG = [&](int k0) {
#pragma unroll
        for (int q = 0; q < 2; q++) {
            size_t off = (size_t)arow * INTER + k0 + (aq + q) * 8;
            pfAh[q] = *(const uint4*)(g_ahi + off);
            pfAl[q] = *(const uint4*)(g_alo + off);
        }
        const float* bsrc = wd + (size_t)e * INTER * HIDDEN + (size_t)(k0 + br) * HIDDEN + n0 + bc;
#pragma unroll
        for (int j = 0; j < 4; j++) pfB[j] = *(const float4*)(bsrc + j * 4);
    };
    auto STORES = [&]() {
#pragma unroll
        for (int q = 0; q < 2; q++) {
            *(uint4*)(Ahi + ar * LDA + (aq + q) * 8) = pfAh[q];
            *(uint4*)(Alo + ar * LDA + (aq + q) * 8) = pfAl[q];
        }
#pragma unroll
        for (int j = 0; j < 4; j++)
            split4s(pfB[j], Bh + br * LDB2 + bc + j * 4, Bl + br * LDB2 + bc + j * 4);
    };

    LOADG(0);
    const int NS = INTER / 32;   // 44
    for (int s = 0; s < NS; s++) {
        STORES();
        __syncthreads();
        if (s + 1 < NS) LOADG((s + 1) * 32);
#pragma unroll
        for (int kk = 0; kk < 32; kk += 16) {
            FragA ah[2], al[2];
#pragma unroll
            for (int mt = 0; mt < 2; mt++) {
                wmma::load_matrix_sync(ah[mt], Ahi + (wm + mt * 16) * LDA + kk, LDA);
                wmma::load_matrix_sync(al[mt], Alo + (wm + mt * 16) * LDA + kk, LDA);
            }
#pragma unroll
            for (int nt = 0; nt < 4; nt++) {
                FragB bh, bl;
                const int bcol = wn + nt * 16;
                wmma::load_matrix_sync(bh, Bh + kk * LDB2 + bcol, LDB2);
                wmma::load_matrix_sync(bl, Bl + kk * LDB2 + bcol, LDB2);
#pragma unroll
                for (int mt = 0; mt < 2; mt++) {
                    wmma::mma_sync(acc[mt][nt], ah[mt], bh, acc[mt][nt]);
                    wmma::mma_sync(acc[mt][nt], al[mt], bh, acc[mt][nt]);
                    wmma::mma_sync(acc[mt][nt], ah[mt], bl, acc[mt][nt]);
                }
            }
        }
        __syncthreads();
    }

    // weighted scatter via per-warp staging
    float* stg = (float*)sm + wid * 320;   // 16x20 per warp
#pragma unroll
    for (int mt = 0; mt < 2; mt++)
#pragma unroll
        for (int nt = 0; nt < 4; nt++) {
            wmma::store_matrix_sync(stg, acc[mt][nt], 20, wmma::mem_row_major);
            __syncwarp();
            for (int i = lane; i < 256; i += 32) {
                int r = i >> 4, c = i & 15;
                int m = m0 + wm + mt * 16 + r;
                if (m < cnt) {
                    int   t = g_tok[base + m];
                    float w = g_w[base + m];
                    atomicAdd(out + (size_t)t * HIDDEN + n0 + wn + nt * 16 + c,
                              w * stg[r * 20 + c]);
                }
            }
            __syncwarp();
        }
}

// ---------------- launch ------------------------------------------------------------
extern "C" void kernel_launch(void* const* d_in, const int* in_sizes, int n_in,
                              void* d_out, int out_size) {
    (void)in_sizes; (void)n_in; (void)out_size;
    const float* hidden = (const float*)d_in[0];
    const float* logits = (const float*)d_in[1];
    const float* wg     = (const float*)d_in[2];
    const float* wu     = (const float*)d_in[3];
    const float* wd     = (const float*)d_in[4];
    float* out = (float*)d_out;

    zero_kernel<<<(TOKENS * HIDDEN + 255) / 256, 256>>>(out);
    route_kernel<<<(TOKENS + 255) / 256, 256>>>(logits);
    scan_kernel<<<1, 32>>>();
    place_kernel<<<(TOKENS + 255) / 256, 256>>>();

    dim3 g1(INTER / 64, (TOKENS + 127) / 128, NE);    // (22, 32, 16)
    gemm1_wmma<<<g1, 256, G1_SMEM>>>(hidden, wg, wu);

    dim3 g2(HIDDEN / 128, (TOKENS + 127) / 128, NE);  // (16, 32, 16)
    gemm2_wmma<<<g2, 256, G2_SMEM>>>(wd, out);
}

// round 9
// speedup vs baseline: 1.2523x; 1.2523x over previous
#include <cuda_runtime.h>
#include <cuda_bf16.h>
#include <mma.h>
#include <math.h>
#include <stdint.h>

using namespace nvcuda;

#define TOKENS 4096
#define HIDDEN 2048
#define INTER  1408
#define NE     16
#define TOPK   2
#define MAXROWS (TOKENS * TOPK)

// ---------------- scratch (SMALL statics only — proven envelope) ---------------
__device__ int   g_count[NE];
__device__ int   g_offset[NE + 1];
__device__ int   g_cursor[NE];
__device__ int   g_te[TOKENS * TOPK];
__device__ float g_tw[TOKENS * TOPK];
__device__ int   g_tok[MAXROWS];
__device__ float g_w[MAXROWS];
// activations as bf16 hi/lo
__device__ __align__(128) __nv_bfloat16 g_ahi[(size_t)MAXROWS * INTER];
__device__ __align__(128) __nv_bfloat16 g_alo[(size_t)MAXROWS * INTER];

// ---------------- helpers ------------------------------------------------------
__device__ __forceinline__ void split4s(float4 v,
                                        __nv_bfloat16* hp, __nv_bfloat16* lp) {
    __nv_bfloat162 h01 = __floats2bfloat162_rn(v.x, v.y);
    __nv_bfloat162 h23 = __floats2bfloat162_rn(v.z, v.w);
    float2 f01 = __bfloat1622float2(h01);
    float2 f23 = __bfloat1622float2(h23);
    __nv_bfloat162 l01 = __floats2bfloat162_rn(v.x - f01.x, v.y - f01.y);
    __nv_bfloat162 l23 = __floats2bfloat162_rn(v.z - f23.x, v.w - f23.y);
    *(uint2*)hp = make_uint2(*(uint32_t*)&h01, *(uint32_t*)&h23);
    *(uint2*)lp = make_uint2(*(uint32_t*)&l01, *(uint32_t*)&l23);
}

typedef wmma::fragment<wmma::matrix_a, 16, 16, 16, __nv_bfloat16, wmma::row_major> FragA;
typedef wmma::fragment<wmma::matrix_b, 16, 16, 16, __nv_bfloat16, wmma::row_major> FragB;
typedef wmma::fragment<wmma::accumulator, 16, 16, 16, float> FragC;

// ---------------- kernel 1: zero output + counters ------------------------------
__global__ void zero_kernel(float* __restrict__ out) {
    int i = blockIdx.x * blockDim.x + threadIdx.x;
    if (i < TOKENS * HIDDEN) out[i] = 0.0f;
    if (i < NE) g_count[i] = 0;
}

// ---------------- kernel 2: routing ----------------------------------------------
__global__ void route_kernel(const float* __restrict__ logits) {
    int t = blockIdx.x * blockDim.x + threadIdx.x;
    if (t >= TOKENS) return;
    const float* l = logits + (size_t)t * NE;
    int i0 = 0; float m0 = l[0];
#pragma unroll
    for (int i = 1; i < NE; i++) { float x = l[i]; if (x > m0) { m0 = x; i0 = i; } }
    int i1 = (i0 == 0) ? 1 : 0; float m1 = l[i1];
#pragma unroll
    for (int i = 0; i < NE; i++) {
        if (i == i0) continue;
        float x = l[i];
        if (x > m1) { m1 = x; i1 = i; }
    }
    float e  = expf(m1 - m0);
    float w0 = 1.0f / (1.0f + e);
    float w1 = e * w0;
    g_te[t * 2 + 0] = i0;  g_tw[t * 2 + 0] = w0;
    g_te[t * 2 + 1] = i1;  g_tw[t * 2 + 1] = w1;
    atomicAdd(&g_count[i0], 1);
    atomicAdd(&g_count[i1], 1);
}

// ---------------- kernel 3: tiny serial scan -------------------------------------
__global__ void scan_kernel() {
    if (threadIdx.x == 0) {
        int acc = 0;
        g_offset[0] = 0;
        for (int i = 0; i < NE; i++) {
            acc += g_count[i];
            g_offset[i + 1] = acc;
            g_cursor[i] = 0;
        }
    }
}

// ---------------- kernel 4: placement ---------------------------------------------
__global__ void place_kernel() {
    int t = blockIdx.x * blockDim.x + threadIdx.x;
    if (t >= TOKENS) return;
#pragma unroll
    for (int k = 0; k < TOPK; k++) {
        int   e = g_te[t * 2 + k];
        float w = g_tw[t * 2 + k];
        int pos = atomicAdd(&g_cursor[e], 1);
        int idx = g_offset[e] + pos;
        g_tok[idx] = t;
        g_w[idx]   = w;
    }
}

// ================ GEMM1: gate+up, wmma bf16x3, BK=16, 2-stage pipeline ==========
// BM=128, BN=64, BK=16. 8 warps: 4(m) x 2(n), warp tile 32x32.
// Stage (bytes): Ahi 6144 | Alo 6144 | Bgh 2304 | Bgl 2304 | Buh 2304 | Bul 2304 = 21504
// smem: toks 512 | stage0 | stage1  = 43520 < 48K
#define LDA 24
#define LDB 72
#define G1_STG  21504
#define G1_SMEM (512 + 2 * G1_STG)

__global__ __launch_bounds__(256) void gemm1_wmma(
    const float* __restrict__ hid,
    const float* __restrict__ wg,
    const float* __restrict__ wu)
{
    const int e   = blockIdx.z;
    const int cnt = g_count[e];
    const int m0  = blockIdx.y * 128;
    if (m0 >= cnt) return;
    const int n0   = blockIdx.x * 64;
    const int base = g_offset[e];

    extern __shared__ char sm[];
    int* toks = (int*)sm;

    const int tid  = threadIdx.x;
    const int wid  = tid >> 5, lane = tid & 31;
    const int wm   = (wid & 3) * 32;
    const int wn   = (wid >> 2) * 32;

    if (tid < 128) {
        int r = m0 + tid;
        toks[tid] = g_tok[base + ((r < cnt) ? r : 0)];
    }
    __syncthreads();

    FragC accg[2][2], accu[2][2];
#pragma unroll
    for (int mt = 0; mt < 2; mt++)
#pragma unroll
        for (int nt = 0; nt < 2; nt++) {
            wmma::fill_fragment(accg[mt][nt], 0.0f);
            wmma::fill_fragment(accu[mt][nt], 0.0f);
        }

    // loader indices: A 128x16 fp32 -> 512 float4, 2/thread; B 16x64 -> 1/thread
    const int ar0 = tid >> 2,  ac0 = (tid & 3) * 4;           // slot 0
    const int ar1 = (tid + 256) >> 2, ac1 = ac0;              // slot 1
    const int brow = tid >> 4, bc4 = (tid & 15) * 4;

    float4 pfA0, pfA1, pfG, pfU;

    auto LOADG = [&](int k0) {
        pfA0 = *(const float4*)(hid + (size_t)toks[ar0] * HIDDEN + k0 + ac0);
        pfA1 = *(const float4*)(hid + (size_t)toks[ar1] * HIDDEN + k0 + ac1);
        size_t off = (size_t)e * HIDDEN * INTER + (size_t)(k0 + brow) * INTER + n0 + bc4;
        pfG = *(const float4*)(wg + off);
        pfU = *(const float4*)(wu + off);
    };
    auto STORES = [&](int b) {
        char* st = sm + 512 + b * G1_STG;
        __nv_bfloat16* Ahi = (__nv_bfloat16*)(st);
        __nv_bfloat16* Alo = (__nv_bfloat16*)(st + 6144);
        __nv_bfloat16* Bgh = (__nv_bfloat16*)(st + 12288);
        __nv_bfloat16* Bgl = (__nv_bfloat16*)(st + 14592);
        __nv_bfloat16* Buh = (__nv_bfloat16*)(st + 16896);
        __nv_bfloat16* Bul = (__nv_bfloat16*)(st + 19200);
        split4s(pfA0, Ahi + ar0 * LDA + ac0, Alo + ar0 * LDA + ac0);
        split4s(pfA1, Ahi + ar1 * LDA + ac1, Alo + ar1 * LDA + ac1);
        split4s(pfG,  Bgh + brow * LDB + bc4, Bgl + brow * LDB + bc4);
        split4s(pfU,  Buh + brow * LDB + bc4, Bul + brow * LDB + bc4);
    };

    const int NS = HIDDEN / 16;   // 128
    LOADG(0);
    STORES(0);
    LOADG(16);
    __syncthreads();

    for (int s = 0; s < NS; s++) {
        if (s + 1 < NS) STORES((s + 1) & 1);
        if (s + 2 < NS) LOADG((s + 2) * 16);

        const char* st = sm + 512 + (s & 1) * G1_STG;
        const __nv_bfloat16* Ahi = (const __nv_bfloat16*)(st);
        const __nv_bfloat16* Alo = (const __nv_bfloat16*)(st + 6144);
        const __nv_bfloat16* Bgh = (const __nv_bfloat16*)(st + 12288);
        const __nv_bfloat16* Bgl = (const __nv_bfloat16*)(st + 14592);
        const __nv_bfloat16* Buh = (const __nv_bfloat16*)(st + 16896);
        const __nv_bfloat16* Bul = (const __nv_bfloat16*)(st + 19200);

        FragA ah[2], al[2];
#pragma unroll
        for (int mt = 0; mt < 2; mt++) {
            wmma::load_matrix_sync(ah[mt], Ahi + (wm + mt * 16) * LDA, LDA);
            wmma::load_matrix_sync(al[mt], Alo + (wm + mt * 16) * LDA, LDA);
        }
#pragma unroll
        for (int nt = 0; nt < 2; nt++) {
            FragB bh, bl;
            const int bcol = wn + nt * 16;
            wmma::load_matrix_sync(bh, Bgh + bcol, LDB);
            wmma::load_matrix_sync(bl, Bgl + bcol, LDB);
#pragma unroll
            for (int mt = 0; mt < 2; mt++) {
                wmma::mma_sync(accg[mt][nt], ah[mt], bh, accg[mt][nt]);
                wmma::mma_sync(accg[mt][nt], al[mt], bh, accg[mt][nt]);
                wmma::mma_sync(accg[mt][nt], ah[mt], bl, accg[mt][nt]);
            }
            wmma::load_matrix_sync(bh, Buh + bcol, LDB);
            wmma::load_matrix_sync(bl, Bul + bcol, LDB);
#pragma unroll
            for (int mt = 0; mt < 2; mt++) {
                wmma::mma_sync(accu[mt][nt], ah[mt], bh, accu[mt][nt]);
                wmma::mma_sync(accu[mt][nt], al[mt], bh, accu[mt][nt]);
                wmma::mma_sync(accu[mt][nt], ah[mt], bl, accu[mt][nt]);
            }
        }
        __syncthreads();
    }

    // epilogue: swiglu in fragments, stage fp32, store bf16 hi/lo activation pairs
    float* stg = (float*)(sm + 512) + wid * 320;   // 16x20 per warp
#pragma unroll
    for (int mt = 0; mt < 2; mt++)
#pragma unroll
        for (int nt = 0; nt < 2; nt++) {
            FragC& G = accg[mt][nt];
            FragC& U = accu[mt][nt];
#pragma unroll
            for (int i = 0; i < G.num_elements; i++) {
                float g = G.x[i];
                G.x[i] = (g / (1.0f + __expf(-g))) * U.x[i];
            }
            wmma::store_matrix_sync(stg, G, 20, wmma::mem_row_major);
            __syncwarp();
            for (int i = lane; i < 128; i += 32) {
                int r = i >> 3, c = (i & 7) * 2;
                int m = m0 + wm + mt * 16 + r;
                if (m < cnt) {
                    float a0 = stg[r * 20 + c], a1 = stg[r * 20 + c + 1];
                    __nv_bfloat162 hv = __floats2bfloat162_rn(a0, a1);
                    float2 hf = __bfloat1622float2(hv);
                    __nv_bfloat162 lv = __floats2bfloat162_rn(a0 - hf.x, a1 - hf.y);
                    size_t off = (size_t)(base + m) * INTER + n0 + wn + nt * 16 + c;
                    *(__nv_bfloat162*)(g_ahi + off) = hv;
                    *(__nv_bfloat162*)(g_alo + off) = lv;
                }
            }
            __syncwarp();
        }
}

// ================ GEMM2: down, wmma bf16x3, BK=16, 2-stage pipeline =============
// BM=128, BN=64. Stage: Ahi 6144 | Alo 6144 | Bh 2304 | Bl 2304 = 16896; x2 = 33792
#define G2_STG  16896
#define G2_SMEM (2 * G2_STG)

__global__ __launch_bounds__(256) void gemm2_wmma(
    const float* __restrict__ wd, float* __restrict__ out)
{
    const int e   = blockIdx.z;
    const int cnt = g_count[e];
    const int m0  = blockIdx.y * 128;
    if (m0 >= cnt) return;
    const int n0   = blockIdx.x * 64;
    const int base = g_offset[e];

    extern __shared__ char sm[];

    const int tid  = threadIdx.x;
    const int wid  = tid >> 5, lane = tid & 31;
    const int wm   = (wid & 3) * 32;
    const int wn   = (wid >> 2) * 32;

    // A loader: 128 rows x 16 bf16 (2 uint4 chunks/row), 1 per thread
    const int ar = tid >> 1;
    const int aq = (tid & 1) * 8;
    int arm = m0 + ar;
    const int arow = base + ((arm < cnt) ? arm : 0);
    // B loader: 16 rows x 64 fp32, 1 float4 per thread
    const int brow = tid >> 4, bc4 = (tid & 15) * 4;

    FragC acc[2][2];
#pragma unroll
    for (int mt = 0; mt < 2; mt++)
#pragma unroll
        for (int nt = 0; nt < 2; nt++) wmma::fill_fragment(acc[mt][nt], 0.0f);

    uint4 pfAh, pfAl;
    float4 pfB;

    auto LOADG = [&](int k0) {
        size_t off = (size_t)arow * INTER + k0 + aq;
        pfAh = *(const uint4*)(g_ahi + off);
        pfAl = *(const uint4*)(g_alo + off);
        pfB  = *(const float4*)(wd + (size_t)e * INTER * HIDDEN +
                                (size_t)(k0 + brow) * HIDDEN + n0 + bc4);
    };
    auto STORES = [&](int b) {
        char* st = sm + b * G2_STG;
        __nv_bfloat16* Ahi = (__nv_bfloat16*)(st);
        __nv_bfloat16* Alo = (__nv_bfloat16*)(st + 6144);
        __nv_bfloat16* Bh  = (__nv_bfloat16*)(st + 12288);
        __nv_bfloat16* Bl  = (__nv_bfloat16*)(st + 14592);
        *(uint4*)(Ahi + ar * LDA + aq) = pfAh;
        *(uint4*)(Alo + ar * LDA + aq) = pfAl;
        split4s(pfB, Bh + brow * LDB + bc4, Bl + brow * LDB + bc4);
    };

    const int NS = INTER / 16;   // 88
    LOADG(0);
    STORES(0);
    LOADG(16);
    __syncthreads();

    for (int s = 0; s < NS; s++) {
        if (s + 1 < NS) STORES((s + 1) & 1);
        if (s + 2 < NS) LOADG((s + 2) * 16);

        const char* st = sm + (s & 1) * G2_STG;
        const __nv_bfloat16* Ahi = (const __nv_bfloat16*)(st);
        const __nv_bfloat16* Alo = (const __nv_bfloat16*)(st + 6144);
        const __nv_bfloat16* Bh  = (const __nv_bfloat16*)(st + 12288);
        const __nv_bfloat16* Bl  = (const __nv_bfloat16*)(st + 14592);

        FragA ah[2], al[2];
#pragma unroll
        for (int mt = 0; mt < 2; mt++) {
            wmma::load_matrix_sync(ah[mt], Ahi + (wm + mt * 16) * LDA, LDA);
            wmma::load_matrix_sync(al[mt], Alo + (wm + mt * 16) * LDA, LDA);
        }
#pragma unroll
        for (int nt = 0; nt < 2; nt++) {
            FragB bh, bl;
            const int bcol = wn + nt * 16;
            wmma::load_matrix_sync(bh, Bh + bcol, LDB);
            wmma::load_matrix_sync(bl, Bl + bcol, LDB);
#pragma unroll
            for (int mt = 0; mt < 2; mt++) {
                wmma::mma_sync(acc[mt][nt], ah[mt], bh, acc[mt][nt]);
                wmma::mma_sync(acc[mt][nt], al[mt], bh, acc[mt][nt]);
                wmma::mma_sync(acc[mt][nt], ah[mt], bl, acc[mt][nt]);
            }
        }
        __syncthreads();
    }

    // weighted scatter via per-warp staging
    float* stg = (float*)sm + wid * 320;
#pragma unroll
    for (int mt = 0; mt < 2; mt++)
#pragma unroll
        for (int nt = 0; nt < 2; nt++) {
            wmma::store_matrix_sync(stg, acc[mt][nt], 20, wmma::mem_row_major);
            __syncwarp();
            for (int i = lane; i < 256; i += 32) {
                int r = i >> 4, c = i & 15;
                int m = m0 + wm + mt * 16 + r;
                if (m < cnt) {
                    int   t = g_tok[base + m];
                    float w = g_w[base + m];
                    atomicAdd(out + (size_t)t * HIDDEN + n0 + wn + nt * 16 + c,
                              w * stg[r * 20 + c]);
                }
            }
            __syncwarp();
        }
}

// ---------------- launch ------------------------------------------------------------
extern "C" void kernel_launch(void* const* d_in, const int* in_sizes, int n_in,
                              void* d_out, int out_size) {
    (void)in_sizes; (void)n_in; (void)out_size;
    const float* hidden = (const float*)d_in[0];
    const float* logits = (const float*)d_in[1];
    const float* wg     = (const float*)d_in[2];
    const float* wu     = (const float*)d_in[3];
    const float* wd     = (const float*)d_in[4];
    float* out = (float*)d_out;

    zero_kernel<<<(TOKENS * HIDDEN + 255) / 256, 256>>>(out);
    route_kernel<<<(TOKENS + 255) / 256, 256>>>(logits);
    scan_kernel<<<1, 32>>>();
    place_kernel<<<(TOKENS + 255) / 256, 256>>>();

    dim3 g1(INTER / 64, (TOKENS + 127) / 128, NE);    // (22, 32, 16)
    gemm1_wmma<<<g1, 256, G1_SMEM>>>(hidden, wg, wu);

    dim3 g2(HIDDEN / 64, (TOKENS + 127) / 128, NE);   // (32, 32, 16)
    gemm2_wmma<<<g2, 256, G2_SMEM>>>(wd, out);
}